// round 17
// baseline (speedup 1.0000x reference)
#include <cuda_runtime.h>
#include <cuda_fp16.h>
#include <cstdint>
#include <math.h>

#define B_   16
#define N_   2048
#define FIN  256
#define H_   128
#define TJ   64
#define NTILE (N_ / TJ)      // 32

// Scratch (allocation-free: __device__ globals)
__device__ half     g_whT[B_ * H_ * N_];      // [b][h][n] fp16
__device__ float    g_src[B_ * N_];           // src + b_a folded in
__device__ float    g_dst[B_ * N_];
__device__ float    g_dstmax[B_];
__device__ float2   g_ed[B_ * N_];            // (exp(dst), exp(0.01*dst))
__device__ uint32_t g_adjb[B_ * N_ * 64];     // bit-packed adj, 64 u32 per row

__device__ __forceinline__ uint32_t smem_u32(const void* p) {
    uint32_t a;
    asm("{ .reg .u64 t; cvta.to.shared.u64 t, %1; cvt.u32.u64 %0, t; }" : "=r"(a) : "l"(p));
    return a;
}

#define LDSM4(r0, r1, r2, r3, addr) \
    asm volatile("ldmatrix.sync.aligned.m8n8.x4.shared.b16 {%0,%1,%2,%3}, [%4];" \
                 : "=r"(r0), "=r"(r1), "=r"(r2), "=r"(r3) : "r"(addr))

#define MMA16816(d, a0, a1, a2, a3, b0, b1) \
    asm volatile("mma.sync.aligned.m16n8k16.row.col.f32.f16.f16.f32 " \
                 "{%0,%1,%2,%3}, {%4,%5,%6,%7}, {%8,%9}, {%0,%1,%2,%3};" \
                 : "+f"((d)[0]), "+f"((d)[1]), "+f"((d)[2]), "+f"((d)[3]) \
                 : "r"(a0), "r"(a1), "r"(a2), "r"(a3), "r"(b0), "r"(b1))

#define CP_ASYNC16(dst, src) \
    asm volatile("cp.async.cg.shared.global [%0], [%1], 16;" :: "r"(dst), "l"(src))
#define CP_COMMIT()  asm volatile("cp.async.commit_group;" ::: "memory")
#define CP_WAIT0()   asm volatile("cp.async.wait_group 0;" ::: "memory")

// ---------------------------------------------------------------------------
// Kernel A: wh in registers -> whT fp16 plane + src/dst reductions.
// ---------------------------------------------------------------------------
__global__ __launch_bounds__(256) void k_proj(const float* __restrict__ inp,
                                              const float* __restrict__ W,
                                              const float* __restrict__ bW,
                                              const float* __restrict__ av,
                                              const float* __restrict__ b_a) {
    __shared__ __align__(16) float A_s[32 * 132];
    __shared__ __align__(16) float W_s[32 * 132];
    int t = threadIdx.x;
    int row0 = blockIdx.x * 128;
    int tr = t >> 4, tc = t & 15;

    float acc[8][8];
#pragma unroll
    for (int i = 0; i < 8; i++)
#pragma unroll
        for (int j = 0; j < 8; j++) acc[i][j] = 0.f;

    for (int k0 = 0; k0 < FIN; k0 += 32) {
#pragma unroll
        for (int v = 0; v < 4; v++) {
            int f4 = t + 256 * v;
            int r = f4 >> 3;
            int c = (f4 & 7) * 4;
            float4 a4 = *(const float4*)(inp + (size_t)(row0 + r) * FIN + k0 + c);
            A_s[(c + 0) * 132 + r] = a4.x;
            A_s[(c + 1) * 132 + r] = a4.y;
            A_s[(c + 2) * 132 + r] = a4.z;
            A_s[(c + 3) * 132 + r] = a4.w;
            float4 b4 = *(const float4*)(W + (size_t)r * FIN + k0 + c);
            W_s[(c + 0) * 132 + r] = b4.x;
            W_s[(c + 1) * 132 + r] = b4.y;
            W_s[(c + 2) * 132 + r] = b4.z;
            W_s[(c + 3) * 132 + r] = b4.w;
        }
        __syncthreads();
#pragma unroll
        for (int kk = 0; kk < 32; kk++) {
            float a[8], b[8];
            *(float4*)&a[0] = *(const float4*)&A_s[kk * 132 + tr * 8];
            *(float4*)&a[4] = *(const float4*)&A_s[kk * 132 + tr * 8 + 4];
            *(float4*)&b[0] = *(const float4*)&W_s[kk * 132 + tc * 8];
            *(float4*)&b[4] = *(const float4*)&W_s[kk * 132 + tc * 8 + 4];
#pragma unroll
            for (int i = 0; i < 8; i++)
#pragma unroll
                for (int j = 0; j < 8; j++)
                    acc[i][j] = fmaf(a[i], b[j], acc[i][j]);
        }
        __syncthreads();
    }

    // ---- epilogue ----
    int h0 = tc * 8;
    int bb = row0 / N_;
    int n0 = (row0 % N_) + tr * 8;

    float bwv[8];
    *(float4*)&bwv[0] = *(const float4*)(bW + h0);
    *(float4*)&bwv[4] = *(const float4*)(bW + h0 + 4);
#pragma unroll
    for (int i = 0; i < 8; i++)
#pragma unroll
        for (int j = 0; j < 8; j++) acc[i][j] += bwv[j];

    // whT transposed fp16 stores
#pragma unroll
    for (int j = 0; j < 8; j++) {
        __align__(16) half hi8[8];
#pragma unroll
        for (int i = 0; i < 8; i++) hi8[i] = __float2half_rn(acc[i][j]);
        size_t idx = ((size_t)(bb * H_ + h0 + j)) * N_ + n0;
        *(uint4*)(g_whT + idx) = *(uint4*)hi8;
    }

    // src/dst reductions
    float a1v[8], a2v[8];
    *(float4*)&a1v[0] = *(const float4*)(av + h0);
    *(float4*)&a1v[4] = *(const float4*)(av + h0 + 4);
    *(float4*)&a2v[0] = *(const float4*)(av + H_ + h0);
    *(float4*)&a2v[4] = *(const float4*)(av + H_ + h0 + 4);

    float s1[8], s2[8];
#pragma unroll
    for (int i = 0; i < 8; i++) {
        float x1 = 0.f, x2 = 0.f;
#pragma unroll
        for (int j = 0; j < 8; j++) {
            x1 = fmaf(acc[i][j], a1v[j], x1);
            x2 = fmaf(acc[i][j], a2v[j], x2);
        }
        s1[i] = x1; s2[i] = x2;
    }
#pragma unroll
    for (int o = 1; o < 16; o <<= 1) {
#pragma unroll
        for (int i = 0; i < 8; i++) {
            s1[i] += __shfl_xor_sync(~0u, s1[i], o);
            s2[i] += __shfl_xor_sync(~0u, s2[i], o);
        }
    }
    if (tc == 0) {
        float ba = b_a[0];
        int r = row0 + tr * 8;
#pragma unroll
        for (int i = 0; i < 8; i++) {
            g_src[r + i] = s1[i] + ba;
            g_dst[r + i] = s2[i];
        }
    }
}

// ---------------------------------------------------------------------------
// Kernel P: pack adj (int32 0/1) into bitmasks.
// ---------------------------------------------------------------------------
__global__ __launch_bounds__(256) void k_pack(const int* __restrict__ adj) {
    int row = blockIdx.x * 8 + (threadIdx.x >> 5);
    int lane = threadIdx.x & 31;
    const int* r = adj + (size_t)row * N_;
    uint32_t* o = g_adjb + (size_t)row * 64;
#pragma unroll
    for (int g = 0; g < 8; g++) {
        int v[8];
#pragma unroll
        for (int k = 0; k < 8; k++) v[k] = r[g * 256 + k * 32 + lane];
        uint32_t msk[8];
#pragma unroll
        for (int k = 0; k < 8; k++) msk[k] = __ballot_sync(~0u, v[k] > 0);
        if (lane == 0) {
            *(uint4*)(o + g * 8)     = make_uint4(msk[0], msk[1], msk[2], msk[3]);
            *(uint4*)(o + g * 8 + 4) = make_uint4(msk[4], msk[5], msk[6], msk[7]);
        }
    }
}

// ---------------------------------------------------------------------------
// Kernel B2: per-batch dst max + exp tables ed1 = exp(dst), ed0 = exp(.01 dst)
// ---------------------------------------------------------------------------
__global__ __launch_bounds__(256) void k_prep() {
    __shared__ float red[8];
    int b = blockIdx.x, t = threadIdx.x;
    float mx = -1e30f;
#pragma unroll
    for (int v = 0; v < 8; v++) {
        int idx = b * N_ + t + 256 * v;
        float d = g_dst[idx];
        mx = fmaxf(mx, d);
        g_ed[idx] = make_float2(__expf(d), __expf(0.01f * d));
    }
#pragma unroll
    for (int o = 16; o; o >>= 1) mx = fmaxf(mx, __shfl_xor_sync(~0u, mx, o));
    if ((t & 31) == 0) red[t >> 5] = mx;
    __syncthreads();
    if (t == 0) {
        float m2 = red[0];
#pragma unroll
        for (int i = 1; i < 8; i++) m2 = fmaxf(m2, red[i]);
        g_dstmax[b] = m2;
    }
}

// ---------------------------------------------------------------------------
// Kernel C: fused attention. CTA = 256 i-rows x 64 h; each warp owns 32 rows
// (4 fragment rows: rr, rr+8, rr+16, rr+24) x 64 h. Each B LDSM4 now feeds
// 4 MMAs (2 row-sets x 2 n8) -> B smem traffic per output /4. A fragments
// computed per-kc in registers (no P smem), interleaved with MMAs.
//
// smem: W[2]: 0, 9216   ed: 18432 (16KB)   l_s: 34816 (1KB)  total 35840
// ---------------------------------------------------------------------------
#define PB   9216u
#define OED  18432u
#define OLS  34816u
#define DYNB 35840

__global__ __launch_bounds__(256, 2) void k_attn_mma(float* __restrict__ out) {
    extern __shared__ __align__(16) char dyn[];
    uint32_t sb = smem_u32(dyn);

    int t = threadIdx.x;
    int w = t >> 5, lane = t & 31;
    int b = blockIdx.z;
    int ibase = blockIdx.x * 256;
    int hbase = blockIdx.y * 64;

    int rr = 32 * w + (lane >> 2);     // rows rr, rr+8, rr+16, rr+24
    int c4 = lane & 3;

    // per-row constants for the 4 fragment rows
    float E1[4], E0[4], X1[4], l[4];
    float dmx = g_dstmax[b];
#pragma unroll
    for (int r = 0; r < 4; r++) {
        float s = g_src[b * N_ + ibase + rr + 8 * r];
        float mb = s + dmx;
        float m = mb > 0.f ? mb : 0.01f * mb;
        E1[r] = __expf(s - m);
        E0[r] = __expf(0.01f * s - m);
        X1[r] = __expf(-s);
        l[r] = 0.f;
    }

    const uint32_t* mrow[4];
#pragma unroll
    for (int r = 0; r < 4; r++)
        mrow[r] = g_adjb + (size_t)(b * N_ + ibase + rr + 8 * r) * 64;
    const half* whT_b = g_whT + (size_t)b * H_ * N_;

    float C[2][8][4];
#pragma unroll
    for (int s2 = 0; s2 < 2; s2++)
#pragma unroll
        for (int nt = 0; nt < 8; nt++)
#pragma unroll
            for (int c = 0; c < 4; c++) C[s2][nt][c] = 0.f;

    // B-side ldmatrix base (row stride 144B, conflict-free)
    int bn = ((lane >> 4) & 1) * 8 + (lane & 7);
    int bk = ((lane >> 3) & 1) * 8;
    uint32_t b_base = sb + bn * 144 + bk * 2;

    // W staging: 4 threads per row, 2 x 16B chunks each (128B/row, 64 rows)
    int hr = t >> 2, hf = t & 3;
    uint32_t wdst = sb + hr * 144 + hf * 32;
    const half* wsrc = whT_b + (size_t)(hbase + hr) * N_ + hf * 16;

    // ---- prologue: stage W(0), ed table -> smem, masks(0) ----
    CP_ASYNC16(wdst,      wsrc);
    CP_ASYNC16(wdst + 16, wsrc + 8);
    CP_COMMIT();
    {
        float4* ds = (float4*)(dyn + OED);
        const float4* g4 = (const float4*)(g_ed + b * N_);
#pragma unroll
        for (int k = 0; k < 4; k++) ds[t + 256 * k] = g4[t + 256 * k];
    }
    uint2 mn[4];
#pragma unroll
    for (int r = 0; r < 4; r++) mn[r] = *(const uint2*)(mrow[r]);
    __syncthreads();   // ed_s visible

    for (int tile = 0; tile < NTILE; tile++) {
        int s = tile & 1;
        int j0 = tile * TJ;

        uint2 mc[4];
#pragma unroll
        for (int r = 0; r < 4; r++) mc[r] = mn[r];
        if (tile < NTILE - 1) {
#pragma unroll
            for (int r = 0; r < 4; r++) mn[r] = *(const uint2*)(mrow[r] + (tile + 1) * 2);
        }

        CP_WAIT0();        // W(tile) landed
        __syncthreads();   // MMA(tile-1) done with buffer s^1

        // ---- stage W(tile+1) into buffer s^1 (overlaps compute) ----
        if (tile < NTILE - 1) {
            int jn = (tile + 1) * TJ;
            uint32_t off = (s ^ 1) * PB;
            CP_ASYNC16(wdst + off,      wsrc + jn);
            CP_ASYNC16(wdst + off + 16, wsrc + jn + 8);
            CP_COMMIT();
        }

        // ---- per-kc: build A fragments in regs, then MMA ----
        uint32_t aoff = s * PB;
        const float4* e4 = (const float4*)(dyn + OED) + (j0 >> 1);
        int b0 = 2 * c4;
#pragma unroll
        for (int kc = 0; kc < 4; kc++) {
            float4 eA = e4[8 * kc + c4];        // j = 16kc + 2c4, 2c4+1
            float4 eB = e4[8 * kc + c4 + 4];    // j = 16kc + 2c4+8, 2c4+9
            uint32_t af[2][4];
#pragma unroll
            for (int s2 = 0; s2 < 2; s2++) {
                int ra = 2 * s2, rb = 2 * s2 + 1;
                uint32_t slA = ((kc & 2) ? mc[ra].y : mc[ra].x) >> ((kc & 1) * 16);
                uint32_t slB = ((kc & 2) ? mc[rb].y : mc[rb].x) >> ((kc & 1) * 16);
                float p;
                float pA0, pA1, pA2, pA3, pB0, pB1, pB2, pB3;
                p = (eA.x > X1[ra]) ? E1[ra] * eA.x : E0[ra] * eA.y; pA0 = (slA >> (b0 + 0)) & 1 ? p : 0.f;
                p = (eA.z > X1[ra]) ? E1[ra] * eA.z : E0[ra] * eA.w; pA1 = (slA >> (b0 + 1)) & 1 ? p : 0.f;
                p = (eB.x > X1[ra]) ? E1[ra] * eB.x : E0[ra] * eB.y; pA2 = (slA >> (b0 + 8)) & 1 ? p : 0.f;
                p = (eB.z > X1[ra]) ? E1[ra] * eB.z : E0[ra] * eB.w; pA3 = (slA >> (b0 + 9)) & 1 ? p : 0.f;
                p = (eA.x > X1[rb]) ? E1[rb] * eA.x : E0[rb] * eA.y; pB0 = (slB >> (b0 + 0)) & 1 ? p : 0.f;
                p = (eA.z > X1[rb]) ? E1[rb] * eA.z : E0[rb] * eA.w; pB1 = (slB >> (b0 + 1)) & 1 ? p : 0.f;
                p = (eB.x > X1[rb]) ? E1[rb] * eB.x : E0[rb] * eB.y; pB2 = (slB >> (b0 + 8)) & 1 ? p : 0.f;
                p = (eB.z > X1[rb]) ? E1[rb] * eB.z : E0[rb] * eB.w; pB3 = (slB >> (b0 + 9)) & 1 ? p : 0.f;
                l[ra] += pA0 + pA1 + pA2 + pA3;
                l[rb] += pB0 + pB1 + pB2 + pB3;
                half2 h;
                h = __floats2half2_rn(pA0, pA1); af[s2][0] = *(uint32_t*)&h;
                h = __floats2half2_rn(pB0, pB1); af[s2][1] = *(uint32_t*)&h;
                h = __floats2half2_rn(pA2, pA3); af[s2][2] = *(uint32_t*)&h;
                h = __floats2half2_rn(pB2, pB3); af[s2][3] = *(uint32_t*)&h;
            }
#pragma unroll
            for (int np = 0; np < 4; np++) {
                uint32_t Bh0, Bh1, Bh2, Bh3;
                LDSM4(Bh0, Bh1, Bh2, Bh3, b_base + aoff + np * (16 * 144) + kc * 32);
                MMA16816(C[0][np * 2 + 0], af[0][0], af[0][1], af[0][2], af[0][3], Bh0, Bh1);
                MMA16816(C[0][np * 2 + 1], af[0][0], af[0][1], af[0][2], af[0][3], Bh2, Bh3);
                MMA16816(C[1][np * 2 + 0], af[1][0], af[1][1], af[1][2], af[1][3], Bh0, Bh1);
                MMA16816(C[1][np * 2 + 1], af[1][0], af[1][1], af[1][2], af[1][3], Bh2, Bh3);
            }
        }
    }

    // l reduction across the lane quad (4 lanes share each row)
#pragma unroll
    for (int r = 0; r < 4; r++) {
        l[r] += __shfl_xor_sync(~0u, l[r], 1);
        l[r] += __shfl_xor_sync(~0u, l[r], 2);
    }
    float* l_s = (float*)(dyn + OLS);
    if (c4 == 0) {
#pragma unroll
        for (int r = 0; r < 4; r++) l_s[rr + 8 * r] = l[r];
    }
    __syncthreads();

    // ---- epilogue: normalize, ELU, store from fragments ----
    {
        int hoff = c4 * 2;
#pragma unroll
        for (int s2 = 0; s2 < 2; s2++) {
            int rowA = rr + 16 * s2;
            int rowB = rowA + 8;
            float invA = 1.0f / l_s[rowA];
            float invB = 1.0f / l_s[rowB];
            float* orowA = out + ((size_t)(b * N_ + ibase + rowA)) * H_ + hbase;
            float* orowB = out + ((size_t)(b * N_ + ibase + rowB)) * H_ + hbase;
#pragma unroll
            for (int nt = 0; nt < 8; nt++) {
                int h = nt * 8 + hoff;
                float x;
                float2 o;
                x = C[s2][nt][0] * invA; o.x = x > 0.f ? x : expm1f(x);
                x = C[s2][nt][1] * invA; o.y = x > 0.f ? x : expm1f(x);
                *(float2*)(orowA + h) = o;
                x = C[s2][nt][2] * invB; o.x = x > 0.f ? x : expm1f(x);
                x = C[s2][nt][3] * invB; o.y = x > 0.f ? x : expm1f(x);
                *(float2*)(orowB + h) = o;
            }
        }
    }
}

// ---------------------------------------------------------------------------
extern "C" void kernel_launch(void* const* d_in, const int* in_sizes, int n_in,
                              void* d_out, int out_size) {
    const float* inputs = (const float*)d_in[0];
    const int*   adj    = (const int*)d_in[1];
    const float* W      = (const float*)d_in[2];
    const float* bW     = (const float*)d_in[3];
    const float* a      = (const float*)d_in[4];
    const float* b_a    = (const float*)d_in[5];
    float* out = (float*)d_out;

    cudaFuncSetAttribute(k_attn_mma, cudaFuncAttributeMaxDynamicSharedMemorySize, DYNB);

    k_proj<<<(B_ * N_) / 128, 256>>>(inputs, W, bW, a, b_a);
    k_pack<<<(B_ * N_) / 8, 256>>>(adj);
    k_prep<<<B_, 256>>>();
    k_attn_mma<<<dim3(N_ / 256, 2, B_), 256, DYNB>>>(out);
}